// round 4
// baseline (speedup 1.0000x reference)
#include <cuda_runtime.h>
#include <math.h>

#define T_STEPS 64
#define B_ 128
#define H_ 256
#define C_ 256
#define K_ 8
#define L_ 3
#define BK 1024
#define NEGV (-1e30f)

// ------------------------- device scratch (static, no allocs) ---------------
__device__ float g_WpT[H_ * C_];            // Wp transposed: [i][c]
__device__ float g_P0[C_ * 4 * H_];         // emb @ W_ih0^T + b_ih0 + b_hh0
__device__ float g_state[BK * H_];          // [B*K, H]
__device__ float g_h[2][L_][BK * H_];       // ping-pong hidden
__device__ float g_c[2][L_][BK * H_];       // ping-pong cell
__device__ float g_prefix[B_ * K_];
__device__ int   g_choices[B_ * K_ * T_STEPS];
__device__ int   g_src[BK];                 // gather source row (b*K + prev)
__device__ int   g_cls[BK];                 // chosen class per new beam row

// ------------------------- precise, fast-math-immune transcendentals --------
// exp: Cody-Waite reduction + degree-7 Taylor/Horner, pure fmaf. ~1 ulp.
__device__ __forceinline__ float f_exp(float x) {
    const float LOG2E  = 1.4426950408889634f;
    const float LN2_HI = 0.693145751953125f;
    const float LN2_LO = 1.4286067653e-06f;
    float n = rintf(x * LOG2E);
    float r = fmaf(-n, LN2_HI, x);
    r = fmaf(-n, LN2_LO, r);
    float p = 1.9841269841e-4f;             // 1/5040
    p = fmaf(p, r, 1.3888888889e-3f);       // 1/720
    p = fmaf(p, r, 8.3333333333e-3f);       // 1/120
    p = fmaf(p, r, 4.1666666667e-2f);       // 1/24
    p = fmaf(p, r, 1.6666666667e-1f);       // 1/6
    p = fmaf(p, r, 0.5f);
    p = fmaf(p, r, 1.0f);
    p = fmaf(p, r, 1.0f);
    int ni = (int)n;
    if (ni < -250) return 0.0f;
    if (ni >  250) ni = 250;
    int e1 = ni >> 1;
    int e2 = ni - e1;
    float s1 = __int_as_float((e1 + 127) << 23);
    float s2 = __int_as_float((e2 + 127) << 23);
    return p * s1 * s2;
}

__device__ __forceinline__ float f_tanh(float x) {
    float ax = fabsf(x);
    float t;
    if (ax < 0.25f) {
        // odd Taylor: x - x^3/3 + 2x^5/15 - 17x^7/315 + 62x^9/2835
        float x2 = ax * ax;
        float p = 2.1869488536e-2f;          // 62/2835
        p = fmaf(p, x2, -5.3968253968e-2f);  // -17/315
        p = fmaf(p, x2, 1.3333333333e-1f);   // 2/15
        p = fmaf(p, x2, -3.3333333333e-1f);  // -1/3
        t = fmaf(p * x2, ax, ax);
    } else {
        float e = f_exp(2.0f * ax);
        t = 1.0f - __fdiv_rn(2.0f, e + 1.0f);
    }
    return copysignf(t, x);
}

__device__ __forceinline__ float f_sig(float x) {
    return __fdiv_rn(1.0f, 1.0f + f_exp(-x));
}

// ------------------------- Wp transpose ------------------------------------
__global__ void k_transpose(const float* __restrict__ Wp) {
    int idx = blockIdx.x * 256 + threadIdx.x;   // H_*C_ total
    int i = idx >> 8, c = idx & 255;
    g_WpT[i * C_ + c] = Wp[c * H_ + i];
}

// ------------------------- P0 precompute -----------------------------------
__global__ __launch_bounds__(256) void k_p0(const float* __restrict__ emb,
                                            const float* __restrict__ Wih0,
                                            const float* __restrict__ bih0,
                                            const float* __restrict__ bhh0) {
    __shared__ float se[H_];
    int cidx = blockIdx.x;
    se[threadIdx.x] = emb[cidx * H_ + threadIdx.x];
    __syncthreads();
    int t = threadIdx.x;
#pragma unroll
    for (int q = 0; q < 4; q++) {
        int n = q * H_ + t;                       // W row index (gate-major)
        const float4* wr = (const float4*)(Wih0 + (size_t)n * H_);
        float acc = 0.f;
#pragma unroll 8
        for (int k4 = 0; k4 < H_ / 4; k4++) {
            float4 w = wr[k4];
            float4 e = *(const float4*)&se[k4 * 4];
            acc += w.x * e.x + w.y * e.y + w.z * e.z + w.w * e.w;
        }
        g_P0[(size_t)cidx * (4 * H_) + n] = acc + bih0[n] + bhh0[n];
    }
}

// ------------------------- init state / prefix / choices --------------------
__global__ void k_init_misc(const float* __restrict__ x) {
    int idx = blockIdx.x * 256 + threadIdx.x;   // BK*H_ total
    int row = idx >> 8;
    int j = idx & 255;
    int b = row >> 3;
    g_state[idx] = x[b * H_ + j];               // x[0] broadcast over beams
    if (idx < B_ * K_) g_prefix[idx] = ((idx & 7) == 0) ? 0.f : NEGV;
    if (idx < B_ * K_ * T_STEPS) g_choices[idx] = 0;
}

// ------------------------- init LSTM (zero state), one layer ----------------
__global__ __launch_bounds__(256) void k_init_lstm(const float* __restrict__ x,
                                                   const float* __restrict__ Wih,
                                                   const float* __restrict__ bih,
                                                   const float* __restrict__ bhh,
                                                   int layer) {
    __shared__ float si[H_];
    int b = blockIdx.x;
    int t = threadIdx.x;
    const float* in = (layer == 0) ? (x + (size_t)b * H_)
                                   : (&g_h[0][layer - 1][0] + (size_t)(b * K_) * H_);
    si[t] = in[t];
    __syncthreads();
    float g4[4];
#pragma unroll
    for (int q = 0; q < 4; q++) {
        int n = q * H_ + t;
        const float4* wr = (const float4*)(Wih + (size_t)n * H_);
        float acc = 0.f;
#pragma unroll 8
        for (int k4 = 0; k4 < H_ / 4; k4++) {
            float4 w = wr[k4];
            float4 e = *(const float4*)&si[k4 * 4];
            acc += w.x * e.x + w.y * e.y + w.z * e.z + w.w * e.w;
        }
        g4[q] = acc + bih[n] + bhh[n];
    }
    float cn = f_sig(g4[0]) * f_tanh(g4[2]);
    float hn = f_sig(g4[3]) * f_tanh(cn);
#pragma unroll
    for (int kb = 0; kb < K_; kb++) {
        g_h[0][layer][((size_t)b * K_ + kb) * H_ + t] = hn;
        g_c[0][layer][((size_t)b * K_ + kb) * H_ + t] = cn;
    }
}

// ------------------------- projection + log_softmax + top-K -----------------
__global__ __launch_bounds__(256) void k_proj(const float* __restrict__ bp, int t) {
    __shared__ float s_state[K_][H_];
    __shared__ float s_pref[K_];
    __shared__ float s_red[8][K_];
    __shared__ float s_max[K_];
    __shared__ float s_lsum[K_];
    __shared__ float s_redv[8];
    __shared__ int   s_redi[8];
    __shared__ float s_topv[K_];
    __shared__ int   s_topi[K_];
    __shared__ int   s_prev[K_];
    __shared__ int   s_clss[K_];
    __shared__ int   s_ch[K_ * T_STEPS];

    int b = blockIdx.x;
    int tid = threadIdx.x;
    int warp = tid >> 5, lane = tid & 31;

    for (int u = tid; u < K_ * H_; u += 256)
        ((float*)s_state)[u] = g_state[(size_t)b * K_ * H_ + u];
    if (tid < K_) s_pref[tid] = g_prefix[b * K_ + tid];
    __syncthreads();

    int c = tid;
    float acc[K_];
#pragma unroll
    for (int k = 0; k < K_; k++) acc[k] = 0.f;
#pragma unroll 4
    for (int i = 0; i < H_; i++) {
        float w = g_WpT[i * C_ + c];
#pragma unroll
        for (int k = 0; k < K_; k++) acc[k] += s_state[k][i] * w;
    }
    float bb = bp[c];
#pragma unroll
    for (int k = 0; k < K_; k++) acc[k] += bb;

    // per-beam max
    {
        float m[K_];
#pragma unroll
        for (int k = 0; k < K_; k++) {
            float v = acc[k];
            for (int o = 16; o; o >>= 1) v = fmaxf(v, __shfl_xor_sync(0xffffffffu, v, o));
            m[k] = v;
        }
        if (lane == 0)
#pragma unroll
            for (int k = 0; k < K_; k++) s_red[warp][k] = m[k];
        __syncthreads();
        if (tid < K_) {
            float v = s_red[0][tid];
            for (int w2 = 1; w2 < 8; w2++) v = fmaxf(v, s_red[w2][tid]);
            s_max[tid] = v;
        }
        __syncthreads();
    }
    float mx[K_];
#pragma unroll
    for (int k = 0; k < K_; k++) mx[k] = s_max[k];
    // per-beam sum of exp (precise exp)
    {
        float s[K_];
#pragma unroll
        for (int k = 0; k < K_; k++) {
            float v = f_exp(acc[k] - mx[k]);
            for (int o = 16; o; o >>= 1) v += __shfl_xor_sync(0xffffffffu, v, o);
            s[k] = v;
        }
        __syncthreads();
        if (lane == 0)
#pragma unroll
            for (int k = 0; k < K_; k++) s_red[warp][k] = s[k];
        __syncthreads();
        if (tid < K_) {
            float v = 0.f;
            for (int w2 = 0; w2 < 8; w2++) v += s_red[w2][tid];
            s_lsum[tid] = (float)log((double)v);   // precise log
        }
        __syncthreads();
    }
    // joint = prefix + ((logit - max) - log(sum)): same association as jax log_softmax
    float jt[K_];
#pragma unroll
    for (int k = 0; k < K_; k++) jt[k] = s_pref[k] + ((acc[k] - mx[k]) - s_lsum[k]);

    // iterated block argmax (ties -> lowest flat idx, matching jax top_k)
    for (int it = 0; it < K_; it++) {
        float bv = -INFINITY;
        int bi = 0x7fffffff;
#pragma unroll
        for (int k = 0; k < K_; k++) {
            if (jt[k] > bv) { bv = jt[k]; bi = k * C_ + c; }
        }
        for (int o = 16; o; o >>= 1) {
            float ov = __shfl_xor_sync(0xffffffffu, bv, o);
            int   oi = __shfl_xor_sync(0xffffffffu, bi, o);
            if (ov > bv || (ov == bv && oi < bi)) { bv = ov; bi = oi; }
        }
        if (lane == 0) { s_redv[warp] = bv; s_redi[warp] = bi; }
        __syncthreads();
        if (tid == 0) {
            float fv = s_redv[0]; int fi = s_redi[0];
            for (int w2 = 1; w2 < 8; w2++)
                if (s_redv[w2] > fv || (s_redv[w2] == fv && s_redi[w2] < fi)) {
                    fv = s_redv[w2]; fi = s_redi[w2];
                }
            s_topv[it] = fv; s_topi[it] = fi;
        }
        __syncthreads();
        int sel = s_topi[it];
        if ((sel & (C_ - 1)) == c) jt[sel >> 8] = -INFINITY;
    }

    if (tid < K_) {
        int sel = s_topi[tid];
        int prev = sel >> 8;
        int cls = sel & (C_ - 1);
        g_prefix[b * K_ + tid] = s_topv[tid];
        g_src[b * K_ + tid] = b * K_ + prev;
        g_cls[b * K_ + tid] = cls;
        s_prev[tid] = prev;
        s_clss[tid] = cls;
    }
    __syncthreads();
    for (int u = tid; u < K_ * T_STEPS; u += 256) {
        int kq = u >> 6, tt = u & 63;
        s_ch[u] = g_choices[(b * K_ + s_prev[kq]) * T_STEPS + tt];
    }
    __syncthreads();
    for (int u = tid; u < K_ * T_STEPS; u += 256) {
        int kq = u >> 6, tt = u & 63;
        g_choices[(b * K_ + kq) * T_STEPS + tt] = (tt == t) ? s_clss[kq] : s_ch[u];
    }
}

// ------------------------- LSTM layer GEMM + gates --------------------------
template <int LAYER>
__global__ __launch_bounds__(256) void k_lstm(const float* __restrict__ Wih,
                                              const float* __restrict__ Whh,
                                              const float* __restrict__ bih,
                                              const float* __restrict__ bhh,
                                              const float* __restrict__ x,
                                              int rb, int t_next) {
    __shared__ float As[16][64];
    __shared__ float Ws[16][64];
    __shared__ int s_src[64];
    __shared__ int s_cls[64];

    const float* hcur = g_h[rb][LAYER];
    const float* ccur = g_c[rb][LAYER];
    float* hnxt = g_h[1 - rb][LAYER];
    float* cnxt = g_c[1 - rb][LAYER];
    const float* inp = (LAYER == 0) ? (const float*)0 : g_h[1 - rb][LAYER - 1];

    int tid = threadIdx.x;
    int rBase = blockIdx.x * 64;
    int jBase = blockIdx.y * 16;

    if (tid < 64) {
        s_src[tid] = g_src[rBase + tid];
        if (LAYER == 0) s_cls[tid] = g_cls[rBase + tid];
    }
    __syncthreads();

    int row_l = tid >> 2, kq = tid & 3;
    const float* hidPtr = hcur + (size_t)s_src[row_l] * H_;
    const float* inPtr = (LAYER == 0) ? (const float*)0 : inp + (size_t)(rBase + row_l) * H_;

    int n_l = tid >> 2;
    int jl = n_l >> 2, gate = n_l & 3;
    const float* wiRow = Wih + (size_t)(gate * H_ + jBase + jl) * H_;
    const float* whRow = Whh + (size_t)(gate * H_ + jBase + jl) * H_;

    float acc[4][4];
#pragma unroll
    for (int r = 0; r < 4; r++)
#pragma unroll
        for (int q = 0; q < 4; q++) acc[r][q] = 0.f;

    const int KSTART = (LAYER == 0) ? 256 : 0;
    int tx = tid & 15, ty = tid >> 4;

    for (int k0 = KSTART; k0 < 512; k0 += 16) {
        float4 av, wv;
        if (k0 < 256) {
            av = *(const float4*)(inPtr + k0 + kq * 4);
            wv = *(const float4*)(wiRow + k0 + kq * 4);
        } else {
            av = *(const float4*)(hidPtr + (k0 - 256) + kq * 4);
            wv = *(const float4*)(whRow + (k0 - 256) + kq * 4);
        }
        As[kq * 4 + 0][row_l] = av.x; As[kq * 4 + 1][row_l] = av.y;
        As[kq * 4 + 2][row_l] = av.z; As[kq * 4 + 3][row_l] = av.w;
        Ws[kq * 4 + 0][n_l] = wv.x; Ws[kq * 4 + 1][n_l] = wv.y;
        Ws[kq * 4 + 2][n_l] = wv.z; Ws[kq * 4 + 3][n_l] = wv.w;
        __syncthreads();
#pragma unroll
        for (int kk = 0; kk < 16; kk++) {
            float4 a = *(const float4*)&As[kk][ty * 4];
            float4 w = *(const float4*)&Ws[kk][tx * 4];
            acc[0][0] += a.x * w.x; acc[0][1] += a.x * w.y; acc[0][2] += a.x * w.z; acc[0][3] += a.x * w.w;
            acc[1][0] += a.y * w.x; acc[1][1] += a.y * w.y; acc[1][2] += a.y * w.z; acc[1][3] += a.y * w.w;
            acc[2][0] += a.z * w.x; acc[2][1] += a.z * w.y; acc[2][2] += a.z * w.z; acc[2][3] += a.z * w.w;
            acc[3][0] += a.w * w.x; acc[3][1] += a.w * w.y; acc[3][2] += a.w * w.z; acc[3][3] += a.w * w.w;
        }
        __syncthreads();
    }

    int j = jBase + tx;
    float bias[4];
    if (LAYER > 0) {
#pragma unroll
        for (int q = 0; q < 4; q++) bias[q] = bih[q * H_ + j] + bhh[q * H_ + j];
    }
#pragma unroll
    for (int r = 0; r < 4; r++) {
        int rl = ty * 4 + r;
        int row_g = rBase + rl;
        int b = row_g >> 3;
        float gi = acc[r][0], gf = acc[r][1], gg = acc[r][2], go = acc[r][3];
        if (LAYER == 0) {
            const float* p0 = g_P0 + (size_t)s_cls[rl] * (4 * H_);
            gi += p0[0 * H_ + j]; gf += p0[1 * H_ + j];
            gg += p0[2 * H_ + j]; go += p0[3 * H_ + j];
        } else {
            gi += bias[0]; gf += bias[1]; gg += bias[2]; go += bias[3];
        }
        float cold = ccur[(size_t)s_src[rl] * H_ + j];
        float cn = f_sig(gf) * cold + f_sig(gi) * f_tanh(gg);
        float hn = f_sig(go) * f_tanh(cn);
        cnxt[(size_t)row_g * H_ + j] = cn;
        hnxt[(size_t)row_g * H_ + j] = hn;
        if (LAYER == 2)
            g_state[(size_t)row_g * H_ + j] = hn + x[(size_t)t_next * B_ * H_ + b * H_ + j];
    }
}

// ------------------------- output ------------------------------------------
__global__ void k_out(float* __restrict__ out, int n) {
    int i = blockIdx.x * 256 + threadIdx.x;
    if (i >= n) return;
    if (i < B_ * K_ * T_STEPS) out[i] = (float)g_choices[i];
    else if (i < B_ * K_ * T_STEPS + B_ * K_) out[i] = g_prefix[i - B_ * K_ * T_STEPS];
    else out[i] = 0.f;
}

// ------------------------- host --------------------------------------------
extern "C" void kernel_launch(void* const* d_in, const int* in_sizes, int n_in,
                              void* d_out, int out_size) {
    const float* x    = (const float*)d_in[0];
    const float* emb  = (const float*)d_in[1];
    const float* W_ih = (const float*)d_in[2];
    const float* W_hh = (const float*)d_in[3];
    const float* b_ih = (const float*)d_in[4];
    const float* b_hh = (const float*)d_in[5];
    const float* Wp   = (const float*)d_in[6];
    const float* bp   = (const float*)d_in[7];

    const int WSTRIDE = 4 * H_ * H_;
    const int BSTRIDE = 4 * H_;

    k_transpose<<<(H_ * C_) / 256, 256>>>(Wp);
    k_p0<<<C_, 256>>>(emb, W_ih, b_ih, b_hh);
    k_init_misc<<<(BK * H_) / 256, 256>>>(x);
    for (int l = 0; l < L_; l++)
        k_init_lstm<<<B_, 256>>>(x, W_ih + (size_t)l * WSTRIDE,
                                 b_ih + (size_t)l * BSTRIDE,
                                 b_hh + (size_t)l * BSTRIDE, l);

    dim3 g(16, 16);
    for (int t = 0; t < T_STEPS; t++) {
        int rb = t & 1;
        int t_next = (t + 1 < T_STEPS) ? (t + 1) : (T_STEPS - 1);
        k_proj<<<B_, 256>>>(bp, t);
        k_lstm<0><<<g, 256>>>(W_ih, W_hh, b_ih, b_hh, x, rb, t_next);
        k_lstm<1><<<g, 256>>>(W_ih + (size_t)1 * WSTRIDE, W_hh + (size_t)1 * WSTRIDE,
                              b_ih + (size_t)1 * BSTRIDE, b_hh + (size_t)1 * BSTRIDE,
                              x, rb, t_next);
        k_lstm<2><<<g, 256>>>(W_ih + (size_t)2 * WSTRIDE, W_hh + (size_t)2 * WSTRIDE,
                              b_ih + (size_t)2 * BSTRIDE, b_hh + (size_t)2 * BSTRIDE,
                              x, rb, t_next);
    }
    k_out<<<(out_size + 255) / 256, 256>>>((float*)d_out, out_size);
}

// round 6
// speedup vs baseline: 1.0272x; 1.0272x over previous
#include <cuda_runtime.h>
#include <math.h>

#define T_STEPS 64
#define B_ 128
#define H_ 256
#define C_ 256
#define K_ 8
#define L_ 3
#define BK 1024
#define NEGV (-1e30f)

// ------------------------- device scratch (static, no allocs) ---------------
__device__ float g_WpT[H_ * C_];            // Wp transposed: [i][c]
__device__ float g_P0[C_ * 4 * H_];         // emb @ W_ih0^T + b_ih0 + b_hh0
__device__ float g_state[BK * H_];          // [B*K, H]
__device__ float g_h[2][L_][BK * H_];       // ping-pong hidden
__device__ float g_c[2][L_][BK * H_];       // ping-pong cell
__device__ float g_prefix[B_ * K_];
__device__ int   g_choices[B_ * K_ * T_STEPS];
__device__ int   g_src[BK];                 // gather source row (b*K + prev)
__device__ int   g_cls[BK];                 // chosen class per new beam row

// ------------------------- f32x2 packed helpers (sm_103a FFMA2) -------------
typedef unsigned long long u64;

__device__ __forceinline__ u64 fma2(u64 a, u64 b, u64 c) {
    u64 d;
    asm("fma.rn.f32x2 %0, %1, %2, %3;" : "=l"(d) : "l"(a), "l"(b), "l"(c));
    return d;
}
__device__ __forceinline__ u64 bcast2(float x) {
    u64 d; unsigned xi = __float_as_uint(x);
    asm("mov.b64 %0, {%1, %1};" : "=l"(d) : "r"(xi));
    return d;
}
__device__ __forceinline__ float lo2(u64 v) { return __uint_as_float((unsigned)v); }
__device__ __forceinline__ float hi2(u64 v) { return __uint_as_float((unsigned)(v >> 32)); }

// ------------------------- precise, fast-math-immune transcendentals --------
__device__ __forceinline__ float f_exp(float x) {
    const float LOG2E  = 1.4426950408889634f;
    const float LN2_HI = 0.693145751953125f;
    const float LN2_LO = 1.4286067653e-06f;
    float n = rintf(x * LOG2E);
    float r = fmaf(-n, LN2_HI, x);
    r = fmaf(-n, LN2_LO, r);
    float p = 1.9841269841e-4f;
    p = fmaf(p, r, 1.3888888889e-3f);
    p = fmaf(p, r, 8.3333333333e-3f);
    p = fmaf(p, r, 4.1666666667e-2f);
    p = fmaf(p, r, 1.6666666667e-1f);
    p = fmaf(p, r, 0.5f);
    p = fmaf(p, r, 1.0f);
    p = fmaf(p, r, 1.0f);
    int ni = (int)n;
    if (ni < -250) return 0.0f;
    if (ni >  250) ni = 250;
    int e1 = ni >> 1;
    int e2 = ni - e1;
    float s1 = __int_as_float((e1 + 127) << 23);
    float s2 = __int_as_float((e2 + 127) << 23);
    return p * s1 * s2;
}

__device__ __forceinline__ float f_tanh(float x) {
    float ax = fabsf(x);
    float t;
    if (ax < 0.25f) {
        float x2 = ax * ax;
        float p = 2.1869488536e-2f;
        p = fmaf(p, x2, -5.3968253968e-2f);
        p = fmaf(p, x2, 1.3333333333e-1f);
        p = fmaf(p, x2, -3.3333333333e-1f);
        t = fmaf(p * x2, ax, ax);
    } else {
        float e = f_exp(2.0f * ax);
        t = 1.0f - __fdiv_rn(2.0f, e + 1.0f);
    }
    return copysignf(t, x);
}

__device__ __forceinline__ float f_sig(float x) {
    return __fdiv_rn(1.0f, 1.0f + f_exp(-x));
}

// ------------------------- Wp transpose (round-4 exact) ---------------------
__global__ void k_transpose(const float* __restrict__ Wp) {
    int idx = blockIdx.x * 256 + threadIdx.x;   // H_*C_ total
    int i = idx >> 8, c = idx & 255;
    g_WpT[i * C_ + c] = Wp[c * H_ + i];
}

// ------------------------- P0 precompute (round-4 exact) --------------------
__global__ __launch_bounds__(256) void k_p0(const float* __restrict__ emb,
                                            const float* __restrict__ Wih0,
                                            const float* __restrict__ bih0,
                                            const float* __restrict__ bhh0) {
    __shared__ float se[H_];
    int cidx = blockIdx.x;
    se[threadIdx.x] = emb[cidx * H_ + threadIdx.x];
    __syncthreads();
    int t = threadIdx.x;
#pragma unroll
    for (int q = 0; q < 4; q++) {
        int n = q * H_ + t;                       // W row index (gate-major)
        const float4* wr = (const float4*)(Wih0 + (size_t)n * H_);
        float acc = 0.f;
#pragma unroll 8
        for (int k4 = 0; k4 < H_ / 4; k4++) {
            float4 w = wr[k4];
            float4 e = *(const float4*)&se[k4 * 4];
            acc += w.x * e.x + w.y * e.y + w.z * e.z + w.w * e.w;
        }
        g_P0[(size_t)cidx * (4 * H_) + n] = acc + bih0[n] + bhh0[n];
    }
}

// ------------------------- init state / prefix / choices --------------------
__global__ void k_init_misc(const float* __restrict__ x) {
    int idx = blockIdx.x * 256 + threadIdx.x;   // BK*H_ total
    int row = idx >> 8;
    int j = idx & 255;
    int b = row >> 3;
    g_state[idx] = x[b * H_ + j];               // x[0] broadcast over beams
    if (idx < B_ * K_) g_prefix[idx] = ((idx & 7) == 0) ? 0.f : NEGV;
    if (idx < B_ * K_ * T_STEPS) g_choices[idx] = 0;
}

// ------------------------- init LSTM (round-4 exact) ------------------------
__global__ __launch_bounds__(256) void k_init_lstm(const float* __restrict__ x,
                                                   const float* __restrict__ Wih,
                                                   const float* __restrict__ bih,
                                                   const float* __restrict__ bhh,
                                                   int layer) {
    __shared__ float si[H_];
    int b = blockIdx.x;
    int t = threadIdx.x;
    const float* in = (layer == 0) ? (x + (size_t)b * H_)
                                   : (&g_h[0][layer - 1][0] + (size_t)(b * K_) * H_);
    si[t] = in[t];
    __syncthreads();
    float g4[4];
#pragma unroll
    for (int q = 0; q < 4; q++) {
        int n = q * H_ + t;
        const float4* wr = (const float4*)(Wih + (size_t)n * H_);
        float acc = 0.f;
#pragma unroll 8
        for (int k4 = 0; k4 < H_ / 4; k4++) {
            float4 w = wr[k4];
            float4 e = *(const float4*)&si[k4 * 4];
            acc += w.x * e.x + w.y * e.y + w.z * e.z + w.w * e.w;
        }
        g4[q] = acc + bih[n] + bhh[n];
    }
    float cn = f_sig(g4[0]) * f_tanh(g4[2]);
    float hn = f_sig(g4[3]) * f_tanh(cn);
#pragma unroll
    for (int kb = 0; kb < K_; kb++) {
        g_h[0][layer][((size_t)b * K_ + kb) * H_ + t] = hn;
        g_c[0][layer][((size_t)b * K_ + kb) * H_ + t] = cn;
    }
}

// ------------------------- projection + log_softmax + top-K (round-4 exact) -
__global__ __launch_bounds__(256) void k_proj(const float* __restrict__ bp, int t) {
    __shared__ float s_state[K_][H_];
    __shared__ float s_pref[K_];
    __shared__ float s_red[8][K_];
    __shared__ float s_max[K_];
    __shared__ float s_lsum[K_];
    __shared__ float s_redv[8];
    __shared__ int   s_redi[8];
    __shared__ float s_topv[K_];
    __shared__ int   s_topi[K_];
    __shared__ int   s_prev[K_];
    __shared__ int   s_clss[K_];
    __shared__ int   s_ch[K_ * T_STEPS];

    int b = blockIdx.x;
    int tid = threadIdx.x;
    int warp = tid >> 5, lane = tid & 31;

    for (int u = tid; u < K_ * H_; u += 256)
        ((float*)s_state)[u] = g_state[(size_t)b * K_ * H_ + u];
    if (tid < K_) s_pref[tid] = g_prefix[b * K_ + tid];
    __syncthreads();

    int c = tid;
    float acc[K_];
#pragma unroll
    for (int k = 0; k < K_; k++) acc[k] = 0.f;
#pragma unroll 4
    for (int i = 0; i < H_; i++) {
        float w = g_WpT[i * C_ + c];
#pragma unroll
        for (int k = 0; k < K_; k++) acc[k] += s_state[k][i] * w;
    }
    float bb = bp[c];
#pragma unroll
    for (int k = 0; k < K_; k++) acc[k] += bb;

    // per-beam max
    {
        float m[K_];
#pragma unroll
        for (int k = 0; k < K_; k++) {
            float v = acc[k];
            for (int o = 16; o; o >>= 1) v = fmaxf(v, __shfl_xor_sync(0xffffffffu, v, o));
            m[k] = v;
        }
        if (lane == 0)
#pragma unroll
            for (int k = 0; k < K_; k++) s_red[warp][k] = m[k];
        __syncthreads();
        if (tid < K_) {
            float v = s_red[0][tid];
            for (int w2 = 1; w2 < 8; w2++) v = fmaxf(v, s_red[w2][tid]);
            s_max[tid] = v;
        }
        __syncthreads();
    }
    float mx[K_];
#pragma unroll
    for (int k = 0; k < K_; k++) mx[k] = s_max[k];
    // per-beam sum of exp (precise exp)
    {
        float s[K_];
#pragma unroll
        for (int k = 0; k < K_; k++) {
            float v = f_exp(acc[k] - mx[k]);
            for (int o = 16; o; o >>= 1) v += __shfl_xor_sync(0xffffffffu, v, o);
            s[k] = v;
        }
        __syncthreads();
        if (lane == 0)
#pragma unroll
            for (int k = 0; k < K_; k++) s_red[warp][k] = s[k];
        __syncthreads();
        if (tid < K_) {
            float v = 0.f;
            for (int w2 = 0; w2 < 8; w2++) v += s_red[w2][tid];
            s_lsum[tid] = (float)log((double)v);   // precise log
        }
        __syncthreads();
    }
    float jt[K_];
#pragma unroll
    for (int k = 0; k < K_; k++) jt[k] = s_pref[k] + ((acc[k] - mx[k]) - s_lsum[k]);

    // iterated block argmax (ties -> lowest flat idx, matching jax top_k)
    for (int it = 0; it < K_; it++) {
        float bv = -INFINITY;
        int bi = 0x7fffffff;
#pragma unroll
        for (int k = 0; k < K_; k++) {
            if (jt[k] > bv) { bv = jt[k]; bi = k * C_ + c; }
        }
        for (int o = 16; o; o >>= 1) {
            float ov = __shfl_xor_sync(0xffffffffu, bv, o);
            int   oi = __shfl_xor_sync(0xffffffffu, bi, o);
            if (ov > bv || (ov == bv && oi < bi)) { bv = ov; bi = oi; }
        }
        if (lane == 0) { s_redv[warp] = bv; s_redi[warp] = bi; }
        __syncthreads();
        if (tid == 0) {
            float fv = s_redv[0]; int fi = s_redi[0];
            for (int w2 = 1; w2 < 8; w2++)
                if (s_redv[w2] > fv || (s_redv[w2] == fv && s_redi[w2] < fi)) {
                    fv = s_redv[w2]; fi = s_redi[w2];
                }
            s_topv[it] = fv; s_topi[it] = fi;
        }
        __syncthreads();
        int sel = s_topi[it];
        if ((sel & (C_ - 1)) == c) jt[sel >> 8] = -INFINITY;
    }

    if (tid < K_) {
        int sel = s_topi[tid];
        int prev = sel >> 8;
        int cls = sel & (C_ - 1);
        g_prefix[b * K_ + tid] = s_topv[tid];
        g_src[b * K_ + tid] = b * K_ + prev;
        g_cls[b * K_ + tid] = cls;
        s_prev[tid] = prev;
        s_clss[tid] = cls;
    }
    __syncthreads();
    for (int u = tid; u < K_ * T_STEPS; u += 256) {
        int kq = u >> 6, tt = u & 63;
        s_ch[u] = g_choices[(b * K_ + s_prev[kq]) * T_STEPS + tt];
    }
    __syncthreads();
    for (int u = tid; u < K_ * T_STEPS; u += 256) {
        int kq = u >> 6, tt = u & 63;
        g_choices[(b * K_ + kq) * T_STEPS + tt] = (tt == t) ? s_clss[kq] : s_ch[u];
    }
}

// ------------------------- LSTM layer GEMM + gates (FFMA2 inner, bit-exact) -
template <int LAYER>
__global__ __launch_bounds__(256) void k_lstm(const float* __restrict__ Wih,
                                              const float* __restrict__ Whh,
                                              const float* __restrict__ bih,
                                              const float* __restrict__ bhh,
                                              const float* __restrict__ x,
                                              int rb, int t_next) {
    __shared__ __align__(16) float As[16][64];
    __shared__ __align__(16) float Ws[16][64];
    __shared__ int s_src[64];
    __shared__ int s_cls[64];

    const float* hcur = g_h[rb][LAYER];
    const float* ccur = g_c[rb][LAYER];
    float* hnxt = g_h[1 - rb][LAYER];
    float* cnxt = g_c[1 - rb][LAYER];
    const float* inp = (LAYER == 0) ? (const float*)0 : g_h[1 - rb][LAYER - 1];

    int tid = threadIdx.x;
    int rBase = blockIdx.x * 64;
    int jBase = blockIdx.y * 16;

    if (tid < 64) {
        s_src[tid] = g_src[rBase + tid];
        if (LAYER == 0) s_cls[tid] = g_cls[rBase + tid];
    }
    __syncthreads();

    int row_l = tid >> 2, kq = tid & 3;
    const float* hidPtr = hcur + (size_t)s_src[row_l] * H_;
    const float* inPtr = (LAYER == 0) ? (const float*)0 : inp + (size_t)(rBase + row_l) * H_;

    int n_l = tid >> 2;
    int jl = n_l >> 2, gate = n_l & 3;
    const float* wiRow = Wih + (size_t)(gate * H_ + jBase + jl) * H_;
    const float* whRow = Whh + (size_t)(gate * H_ + jBase + jl) * H_;

    // acc2[r][0] lanes = (gate q0, q1); acc2[r][1] lanes = (q2, q3).
    // Per-lane FMA sequence identical to round-4 scalar version -> bit-exact.
    u64 acc2[4][2];
#pragma unroll
    for (int r = 0; r < 4; r++) { acc2[r][0] = 0ull; acc2[r][1] = 0ull; }

    const int KSTART = (LAYER == 0) ? 256 : 0;
    int tx = tid & 15, ty = tid >> 4;

    for (int k0 = KSTART; k0 < 512; k0 += 16) {
        float4 av, wv;
        if (k0 < 256) {
            av = *(const float4*)(inPtr + k0 + kq * 4);
            wv = *(const float4*)(wiRow + k0 + kq * 4);
        } else {
            av = *(const float4*)(hidPtr + (k0 - 256) + kq * 4);
            wv = *(const float4*)(whRow + (k0 - 256) + kq * 4);
        }
        As[kq * 4 + 0][row_l] = av.x; As[kq * 4 + 1][row_l] = av.y;
        As[kq * 4 + 2][row_l] = av.z; As[kq * 4 + 3][row_l] = av.w;
        Ws[kq * 4 + 0][n_l] = wv.x; Ws[kq * 4 + 1][n_l] = wv.y;
        Ws[kq * 4 + 2][n_l] = wv.z; Ws[kq * 4 + 3][n_l] = wv.w;
        __syncthreads();
#pragma unroll
        for (int kk = 0; kk < 16; kk++) {
            float4 a = *(const float4*)&As[kk][ty * 4];
            ulonglong2 w = *(const ulonglong2*)&Ws[kk][tx * 4];
            u64 a0 = bcast2(a.x), a1 = bcast2(a.y), a2 = bcast2(a.z), a3 = bcast2(a.w);
            acc2[0][0] = fma2(a0, w.x, acc2[0][0]); acc2[0][1] = fma2(a0, w.y, acc2[0][1]);
            acc2[1][0] = fma2(a1, w.x, acc2[1][0]); acc2[1][1] = fma2(a1, w.y, acc2[1][1]);
            acc2[2][0] = fma2(a2, w.x, acc2[2][0]); acc2[2][1] = fma2(a2, w.y, acc2[2][1]);
            acc2[3][0] = fma2(a3, w.x, acc2[3][0]); acc2[3][1] = fma2(a3, w.y, acc2[3][1]);
        }
        __syncthreads();
    }

    int j = jBase + tx;
    float bias[4];
    if (LAYER > 0) {
#pragma unroll
        for (int q = 0; q < 4; q++) bias[q] = bih[q * H_ + j] + bhh[q * H_ + j];
    }
#pragma unroll
    for (int r = 0; r < 4; r++) {
        int rl = ty * 4 + r;
        int row_g = rBase + rl;
        int b = row_g >> 3;
        float gi = lo2(acc2[r][0]), gf = hi2(acc2[r][0]);
        float gg = lo2(acc2[r][1]), go = hi2(acc2[r][1]);
        if (LAYER == 0) {
            const float* p0 = g_P0 + (size_t)s_cls[rl] * (4 * H_);
            gi += p0[0 * H_ + j]; gf += p0[1 * H_ + j];
            gg += p0[2 * H_ + j]; go += p0[3 * H_ + j];
        } else {
            gi += bias[0]; gf += bias[1]; gg += bias[2]; go += bias[3];
        }
        float cold = ccur[(size_t)s_src[rl] * H_ + j];
        float cn = f_sig(gf) * cold + f_sig(gi) * f_tanh(gg);
        float hn = f_sig(go) * f_tanh(cn);
        cnxt[(size_t)row_g * H_ + j] = cn;
        hnxt[(size_t)row_g * H_ + j] = hn;
        if (LAYER == 2)
            g_state[(size_t)row_g * H_ + j] = hn + x[(size_t)t_next * B_ * H_ + b * H_ + j];
    }
}

// ------------------------- output ------------------------------------------
__global__ void k_out(float* __restrict__ out, int n) {
    int i = blockIdx.x * 256 + threadIdx.x;
    if (i >= n) return;
    if (i < B_ * K_ * T_STEPS) out[i] = (float)g_choices[i];
    else if (i < B_ * K_ * T_STEPS + B_ * K_) out[i] = g_prefix[i - B_ * K_ * T_STEPS];
    else out[i] = 0.f;
}

// ------------------------- host --------------------------------------------
extern "C" void kernel_launch(void* const* d_in, const int* in_sizes, int n_in,
                              void* d_out, int out_size) {
    const float* x    = (const float*)d_in[0];
    const float* emb  = (const float*)d_in[1];
    const float* W_ih = (const float*)d_in[2];
    const float* W_hh = (const float*)d_in[3];
    const float* b_ih = (const float*)d_in[4];
    const float* b_hh = (const float*)d_in[5];
    const float* Wp   = (const float*)d_in[6];
    const float* bp   = (const float*)d_in[7];

    const int WSTRIDE = 4 * H_ * H_;
    const int BSTRIDE = 4 * H_;

    k_transpose<<<(H_ * C_) / 256, 256>>>(Wp);
    k_p0<<<C_, 256>>>(emb, W_ih, b_ih, b_hh);
    k_init_misc<<<(BK * H_) / 256, 256>>>(x);
    for (int l = 0; l < L_; l++)
        k_init_lstm<<<B_, 256>>>(x, W_ih + (size_t)l * WSTRIDE,
                                 b_ih + (size_t)l * BSTRIDE,
                                 b_hh + (size_t)l * BSTRIDE, l);

    dim3 g(16, 16);
    for (int t = 0; t < T_STEPS; t++) {
        int rb = t & 1;
        int t_next = (t + 1 < T_STEPS) ? (t + 1) : (T_STEPS - 1);
        k_proj<<<B_, 256>>>(bp, t);
        k_lstm<0><<<g, 256>>>(W_ih, W_hh, b_ih, b_hh, x, rb, t_next);
        k_lstm<1><<<g, 256>>>(W_ih + (size_t)1 * WSTRIDE, W_hh + (size_t)1 * WSTRIDE,
                              b_ih + (size_t)1 * BSTRIDE, b_hh + (size_t)1 * BSTRIDE,
                              x, rb, t_next);
        k_lstm<2><<<g, 256>>>(W_ih + (size_t)2 * WSTRIDE, W_hh + (size_t)2 * WSTRIDE,
                              b_ih + (size_t)2 * BSTRIDE, b_hh + (size_t)2 * BSTRIDE,
                              x, rb, t_next);
    }
    k_out<<<(out_size + 255) / 256, 256>>>((float*)d_out, out_size);
}

// round 7
// speedup vs baseline: 1.1565x; 1.1259x over previous
#include <cuda_runtime.h>
#include <math.h>

#define T_STEPS 64
#define B_ 128
#define H_ 256
#define C_ 256
#define K_ 8
#define L_ 3
#define BK 1024
#define NEGV (-1e30f)

// ------------------------- device scratch (static, no allocs) ---------------
__device__ float g_WpT[H_ * C_];            // Wp transposed: [i][c]
__device__ float g_P0[C_ * 4 * H_];         // emb @ W_ih0^T + b_ih0 + b_hh0
__device__ float g_state[BK * H_];          // [B*K, H]
__device__ float g_h[2][L_][BK * H_];       // ping-pong hidden
__device__ float g_c[2][L_][BK * H_];       // ping-pong cell
__device__ float g_prefix[B_ * K_];
__device__ int   g_choices[B_ * K_ * T_STEPS];
__device__ int   g_src[BK];                 // gather source row (b*K + prev)
__device__ int   g_cls[BK];                 // chosen class per new beam row

// ------------------------- f32x2 packed helpers (sm_103a FFMA2) -------------
typedef unsigned long long u64;

__device__ __forceinline__ u64 fma2(u64 a, u64 b, u64 c) {
    u64 d;
    asm("fma.rn.f32x2 %0, %1, %2, %3;" : "=l"(d) : "l"(a), "l"(b), "l"(c));
    return d;
}
__device__ __forceinline__ u64 bcast2(float x) {
    u64 d; unsigned xi = __float_as_uint(x);
    asm("mov.b64 %0, {%1, %1};" : "=l"(d) : "r"(xi));
    return d;
}
__device__ __forceinline__ float lo2(u64 v) { return __uint_as_float((unsigned)v); }
__device__ __forceinline__ float hi2(u64 v) { return __uint_as_float((unsigned)(v >> 32)); }

// ------------------------- precise, fast-math-immune transcendentals --------
__device__ __forceinline__ float f_exp(float x) {
    const float LOG2E  = 1.4426950408889634f;
    const float LN2_HI = 0.693145751953125f;
    const float LN2_LO = 1.4286067653e-06f;
    float n = rintf(x * LOG2E);
    float r = fmaf(-n, LN2_HI, x);
    r = fmaf(-n, LN2_LO, r);
    float p = 1.9841269841e-4f;
    p = fmaf(p, r, 1.3888888889e-3f);
    p = fmaf(p, r, 8.3333333333e-3f);
    p = fmaf(p, r, 4.1666666667e-2f);
    p = fmaf(p, r, 1.6666666667e-1f);
    p = fmaf(p, r, 0.5f);
    p = fmaf(p, r, 1.0f);
    p = fmaf(p, r, 1.0f);
    int ni = (int)n;
    if (ni < -250) return 0.0f;
    if (ni >  250) ni = 250;
    int e1 = ni >> 1;
    int e2 = ni - e1;
    float s1 = __int_as_float((e1 + 127) << 23);
    float s2 = __int_as_float((e2 + 127) << 23);
    return p * s1 * s2;
}

__device__ __forceinline__ float f_tanh(float x) {
    float ax = fabsf(x);
    float t;
    if (ax < 0.25f) {
        float x2 = ax * ax;
        float p = 2.1869488536e-2f;
        p = fmaf(p, x2, -5.3968253968e-2f);
        p = fmaf(p, x2, 1.3333333333e-1f);
        p = fmaf(p, x2, -3.3333333333e-1f);
        t = fmaf(p * x2, ax, ax);
    } else {
        float e = f_exp(2.0f * ax);
        t = 1.0f - __fdiv_rn(2.0f, e + 1.0f);
    }
    return copysignf(t, x);
}

__device__ __forceinline__ float f_sig(float x) {
    return __fdiv_rn(1.0f, 1.0f + f_exp(-x));
}

// ------------------------- Wp transpose (round-4 exact) ---------------------
__global__ void k_transpose(const float* __restrict__ Wp) {
    int idx = blockIdx.x * 256 + threadIdx.x;   // H_*C_ total
    int i = idx >> 8, c = idx & 255;
    g_WpT[i * C_ + c] = Wp[c * H_ + i];
}

// ------------------------- P0 precompute (round-4 exact) --------------------
__global__ __launch_bounds__(256) void k_p0(const float* __restrict__ emb,
                                            const float* __restrict__ Wih0,
                                            const float* __restrict__ bih0,
                                            const float* __restrict__ bhh0) {
    __shared__ float se[H_];
    int cidx = blockIdx.x;
    se[threadIdx.x] = emb[cidx * H_ + threadIdx.x];
    __syncthreads();
    int t = threadIdx.x;
#pragma unroll
    for (int q = 0; q < 4; q++) {
        int n = q * H_ + t;                       // W row index (gate-major)
        const float4* wr = (const float4*)(Wih0 + (size_t)n * H_);
        float acc = 0.f;
#pragma unroll 8
        for (int k4 = 0; k4 < H_ / 4; k4++) {
            float4 w = wr[k4];
            float4 e = *(const float4*)&se[k4 * 4];
            acc += w.x * e.x + w.y * e.y + w.z * e.z + w.w * e.w;
        }
        g_P0[(size_t)cidx * (4 * H_) + n] = acc + bih0[n] + bhh0[n];
    }
}

// ------------------------- init state / prefix / choices --------------------
__global__ void k_init_misc(const float* __restrict__ x) {
    int idx = blockIdx.x * 256 + threadIdx.x;   // BK*H_ total
    int row = idx >> 8;
    int j = idx & 255;
    int b = row >> 3;
    g_state[idx] = x[b * H_ + j];               // x[0] broadcast over beams
    if (idx < B_ * K_) g_prefix[idx] = ((idx & 7) == 0) ? 0.f : NEGV;
    if (idx < B_ * K_ * T_STEPS) g_choices[idx] = 0;
}

// ------------------------- init LSTM (round-4 exact) ------------------------
__global__ __launch_bounds__(256) void k_init_lstm(const float* __restrict__ x,
                                                   const float* __restrict__ Wih,
                                                   const float* __restrict__ bih,
                                                   const float* __restrict__ bhh,
                                                   int layer) {
    __shared__ float si[H_];
    int b = blockIdx.x;
    int t = threadIdx.x;
    const float* in = (layer == 0) ? (x + (size_t)b * H_)
                                   : (&g_h[0][layer - 1][0] + (size_t)(b * K_) * H_);
    si[t] = in[t];
    __syncthreads();
    float g4[4];
#pragma unroll
    for (int q = 0; q < 4; q++) {
        int n = q * H_ + t;
        const float4* wr = (const float4*)(Wih + (size_t)n * H_);
        float acc = 0.f;
#pragma unroll 8
        for (int k4 = 0; k4 < H_ / 4; k4++) {
            float4 w = wr[k4];
            float4 e = *(const float4*)&si[k4 * 4];
            acc += w.x * e.x + w.y * e.y + w.z * e.z + w.w * e.w;
        }
        g4[q] = acc + bih[n] + bhh[n];
    }
    float cn = f_sig(g4[0]) * f_tanh(g4[2]);
    float hn = f_sig(g4[3]) * f_tanh(cn);
#pragma unroll
    for (int kb = 0; kb < K_; kb++) {
        g_h[0][layer][((size_t)b * K_ + kb) * H_ + t] = hn;
        g_c[0][layer][((size_t)b * K_ + kb) * H_ + t] = cn;
    }
}

// ------------------------- projection + log_softmax + top-K (round-4 exact) -
__global__ __launch_bounds__(256) void k_proj(const float* __restrict__ bp, int t) {
    __shared__ float s_state[K_][H_];
    __shared__ float s_pref[K_];
    __shared__ float s_red[8][K_];
    __shared__ float s_max[K_];
    __shared__ float s_lsum[K_];
    __shared__ float s_redv[8];
    __shared__ int   s_redi[8];
    __shared__ float s_topv[K_];
    __shared__ int   s_topi[K_];
    __shared__ int   s_prev[K_];
    __shared__ int   s_clss[K_];
    __shared__ int   s_ch[K_ * T_STEPS];

    int b = blockIdx.x;
    int tid = threadIdx.x;
    int warp = tid >> 5, lane = tid & 31;

    for (int u = tid; u < K_ * H_; u += 256)
        ((float*)s_state)[u] = g_state[(size_t)b * K_ * H_ + u];
    if (tid < K_) s_pref[tid] = g_prefix[b * K_ + tid];
    __syncthreads();

    int c = tid;
    float acc[K_];
#pragma unroll
    for (int k = 0; k < K_; k++) acc[k] = 0.f;
#pragma unroll 4
    for (int i = 0; i < H_; i++) {
        float w = g_WpT[i * C_ + c];
#pragma unroll
        for (int k = 0; k < K_; k++) acc[k] += s_state[k][i] * w;
    }
    float bb = bp[c];
#pragma unroll
    for (int k = 0; k < K_; k++) acc[k] += bb;

    // per-beam max
    {
        float m[K_];
#pragma unroll
        for (int k = 0; k < K_; k++) {
            float v = acc[k];
            for (int o = 16; o; o >>= 1) v = fmaxf(v, __shfl_xor_sync(0xffffffffu, v, o));
            m[k] = v;
        }
        if (lane == 0)
#pragma unroll
            for (int k = 0; k < K_; k++) s_red[warp][k] = m[k];
        __syncthreads();
        if (tid < K_) {
            float v = s_red[0][tid];
            for (int w2 = 1; w2 < 8; w2++) v = fmaxf(v, s_red[w2][tid]);
            s_max[tid] = v;
        }
        __syncthreads();
    }
    float mx[K_];
#pragma unroll
    for (int k = 0; k < K_; k++) mx[k] = s_max[k];
    // per-beam sum of exp (precise exp)
    {
        float s[K_];
#pragma unroll
        for (int k = 0; k < K_; k++) {
            float v = f_exp(acc[k] - mx[k]);
            for (int o = 16; o; o >>= 1) v += __shfl_xor_sync(0xffffffffu, v, o);
            s[k] = v;
        }
        __syncthreads();
        if (lane == 0)
#pragma unroll
            for (int k = 0; k < K_; k++) s_red[warp][k] = s[k];
        __syncthreads();
        if (tid < K_) {
            float v = 0.f;
            for (int w2 = 0; w2 < 8; w2++) v += s_red[w2][tid];
            s_lsum[tid] = (float)log((double)v);   // precise log
        }
        __syncthreads();
    }
    float jt[K_];
#pragma unroll
    for (int k = 0; k < K_; k++) jt[k] = s_pref[k] + ((acc[k] - mx[k]) - s_lsum[k]);

    // iterated block argmax (ties -> lowest flat idx, matching jax top_k)
    for (int it = 0; it < K_; it++) {
        float bv = -INFINITY;
        int bi = 0x7fffffff;
#pragma unroll
        for (int k = 0; k < K_; k++) {
            if (jt[k] > bv) { bv = jt[k]; bi = k * C_ + c; }
        }
        for (int o = 16; o; o >>= 1) {
            float ov = __shfl_xor_sync(0xffffffffu, bv, o);
            int   oi = __shfl_xor_sync(0xffffffffu, bi, o);
            if (ov > bv || (ov == bv && oi < bi)) { bv = ov; bi = oi; }
        }
        if (lane == 0) { s_redv[warp] = bv; s_redi[warp] = bi; }
        __syncthreads();
        if (tid == 0) {
            float fv = s_redv[0]; int fi = s_redi[0];
            for (int w2 = 1; w2 < 8; w2++)
                if (s_redv[w2] > fv || (s_redv[w2] == fv && s_redi[w2] < fi)) {
                    fv = s_redv[w2]; fi = s_redi[w2];
                }
            s_topv[it] = fv; s_topi[it] = fi;
        }
        __syncthreads();
        int sel = s_topi[it];
        if ((sel & (C_ - 1)) == c) jt[sel >> 8] = -INFINITY;
    }

    if (tid < K_) {
        int sel = s_topi[tid];
        int prev = sel >> 8;
        int cls = sel & (C_ - 1);
        g_prefix[b * K_ + tid] = s_topv[tid];
        g_src[b * K_ + tid] = b * K_ + prev;
        g_cls[b * K_ + tid] = cls;
        s_prev[tid] = prev;
        s_clss[tid] = cls;
    }
    __syncthreads();
    for (int u = tid; u < K_ * T_STEPS; u += 256) {
        int kq = u >> 6, tt = u & 63;
        s_ch[u] = g_choices[(b * K_ + s_prev[kq]) * T_STEPS + tt];
    }
    __syncthreads();
    for (int u = tid; u < K_ * T_STEPS; u += 256) {
        int kq = u >> 6, tt = u & 63;
        g_choices[(b * K_ + kq) * T_STEPS + tt] = (tt == t) ? s_clss[kq] : s_ch[u];
    }
}

// ------------------------- LSTM layer GEMM + gates --------------------------
// Tile: 128 rows x 64 gate-cols (16 j x 4 gates), grid 8x16 = 128 blocks.
// Per thread: 8 rows x 4 gates = 16 u64 accumulators. Double-buffered smem,
// one __syncthreads per 16-wide k-tile; LDGs for the next tile issued before
// compute. FMA order per output: k ascending, fma2 pairing (g0,g1)/(g2,g3)
// -> bit-identical to the round-6 passing kernel.
template <int LAYER>
__global__ __launch_bounds__(256) void k_lstm(const float* __restrict__ Wih,
                                              const float* __restrict__ Whh,
                                              const float* __restrict__ bih,
                                              const float* __restrict__ bhh,
                                              const float* __restrict__ x,
                                              int rb, int t_next) {
    __shared__ __align__(16) float As[2][16][128];
    __shared__ __align__(16) float Ws[2][16][64];
    __shared__ int s_src[128];
    __shared__ int s_cls[128];

    const float* hcur = g_h[rb][LAYER];
    const float* ccur = g_c[rb][LAYER];
    float* hnxt = g_h[1 - rb][LAYER];
    float* cnxt = g_c[1 - rb][LAYER];
    const float* inp = (LAYER == 0) ? (const float*)0 : g_h[1 - rb][LAYER - 1];

    int tid = threadIdx.x;
    int rBase = blockIdx.x * 128;
    int jBase = blockIdx.y * 16;

    if (tid < 128) {
        s_src[tid] = g_src[rBase + tid];
        if (LAYER == 0) s_cls[tid] = g_cls[rBase + tid];
    }
    __syncthreads();

    // ---- staging indices ----
    int arow = tid >> 1;            // 0..127: local A row
    int akq  = (tid & 1) * 8;       // k offset within 16-tile (0 or 8)
    int wrow = tid >> 2;            // 0..63: local W col (n_l = j_local*4+gate)
    int wkq  = (tid & 3) * 4;       // k offset (0,4,8,12)

    const float* aHid = hcur + (size_t)s_src[arow] * H_;
    const float* aIn  = (LAYER == 0) ? (const float*)0
                                     : inp + (size_t)(rBase + arow) * H_;
    // n_l = wrow: j_local = wrow>>2, gate = wrow&3 -> W row = gate*H + jBase + j_local
    const size_t wgrow = (size_t)((wrow & 3) * H_ + jBase + (wrow >> 2)) * H_;
    const float* wiP = Wih + wgrow;
    const float* whP = Whh + wgrow;

    const int KSTART = (LAYER == 0) ? 256 : 0;
    const int NT = (512 - KSTART) / 16;

    int tx = tid & 15, ty = tid >> 4;

    u64 acc[8][2];
#pragma unroll
    for (int r = 0; r < 8; r++) { acc[r][0] = 0ull; acc[r][1] = 0ull; }

    // ---- prologue: load tile 0 ----
    float4 a0, a1, w0;
    {
        int k = KSTART + akq;
        const float* p = (LAYER > 0 && k < 256) ? (aIn + k) : (aHid + (k - 256));
        a0 = *(const float4*)p; a1 = *(const float4*)(p + 4);
        int kw = KSTART + wkq;
        const float* q = (LAYER > 0 && kw < 256) ? (wiP + kw) : (whP + (kw - 256));
        w0 = *(const float4*)q;
    }
    {
        As[0][akq + 0][arow] = a0.x; As[0][akq + 1][arow] = a0.y;
        As[0][akq + 2][arow] = a0.z; As[0][akq + 3][arow] = a0.w;
        As[0][akq + 4][arow] = a1.x; As[0][akq + 5][arow] = a1.y;
        As[0][akq + 6][arow] = a1.z; As[0][akq + 7][arow] = a1.w;
        Ws[0][wkq + 0][wrow] = w0.x; Ws[0][wkq + 1][wrow] = w0.y;
        Ws[0][wkq + 2][wrow] = w0.z; Ws[0][wkq + 3][wrow] = w0.w;
    }
    __syncthreads();

    for (int kt = 0; kt < NT; kt++) {
        int buf = kt & 1;
        bool more = (kt + 1 < NT);
        if (more) {
            int k = KSTART + (kt + 1) * 16 + akq;
            const float* p = (LAYER > 0 && k < 256) ? (aIn + k) : (aHid + (k - 256));
            a0 = *(const float4*)p; a1 = *(const float4*)(p + 4);
            int kw = KSTART + (kt + 1) * 16 + wkq;
            const float* q = (LAYER > 0 && kw < 256) ? (wiP + kw) : (whP + (kw - 256));
            w0 = *(const float4*)q;
        }
#pragma unroll
        for (int kk = 0; kk < 16; kk++) {
            float4 av0 = *(const float4*)&As[buf][kk][ty * 8];
            float4 av1 = *(const float4*)&As[buf][kk][ty * 8 + 4];
            ulonglong2 wv = *(const ulonglong2*)&Ws[buf][kk][tx * 4];
            u64 bb;
            bb = bcast2(av0.x); acc[0][0] = fma2(bb, wv.x, acc[0][0]); acc[0][1] = fma2(bb, wv.y, acc[0][1]);
            bb = bcast2(av0.y); acc[1][0] = fma2(bb, wv.x, acc[1][0]); acc[1][1] = fma2(bb, wv.y, acc[1][1]);
            bb = bcast2(av0.z); acc[2][0] = fma2(bb, wv.x, acc[2][0]); acc[2][1] = fma2(bb, wv.y, acc[2][1]);
            bb = bcast2(av0.w); acc[3][0] = fma2(bb, wv.x, acc[3][0]); acc[3][1] = fma2(bb, wv.y, acc[3][1]);
            bb = bcast2(av1.x); acc[4][0] = fma2(bb, wv.x, acc[4][0]); acc[4][1] = fma2(bb, wv.y, acc[4][1]);
            bb = bcast2(av1.y); acc[5][0] = fma2(bb, wv.x, acc[5][0]); acc[5][1] = fma2(bb, wv.y, acc[5][1]);
            bb = bcast2(av1.z); acc[6][0] = fma2(bb, wv.x, acc[6][0]); acc[6][1] = fma2(bb, wv.y, acc[6][1]);
            bb = bcast2(av1.w); acc[7][0] = fma2(bb, wv.x, acc[7][0]); acc[7][1] = fma2(bb, wv.y, acc[7][1]);
        }
        if (more) {
            int nb = buf ^ 1;
            As[nb][akq + 0][arow] = a0.x; As[nb][akq + 1][arow] = a0.y;
            As[nb][akq + 2][arow] = a0.z; As[nb][akq + 3][arow] = a0.w;
            As[nb][akq + 4][arow] = a1.x; As[nb][akq + 5][arow] = a1.y;
            As[nb][akq + 6][arow] = a1.z; As[nb][akq + 7][arow] = a1.w;
            Ws[nb][wkq + 0][wrow] = w0.x; Ws[nb][wkq + 1][wrow] = w0.y;
            Ws[nb][wkq + 2][wrow] = w0.z; Ws[nb][wkq + 3][wrow] = w0.w;
        }
        __syncthreads();
    }

    // ---- epilogue (formulas/order identical to round-6) ----
    int j = jBase + tx;
    float bias[4];
    if (LAYER > 0) {
#pragma unroll
        for (int q = 0; q < 4; q++) bias[q] = bih[q * H_ + j] + bhh[q * H_ + j];
    }
#pragma unroll
    for (int r = 0; r < 8; r++) {
        int rl = ty * 8 + r;
        int row_g = rBase + rl;
        int b = row_g >> 3;
        float gi = lo2(acc[r][0]), gf = hi2(acc[r][0]);
        float gg = lo2(acc[r][1]), go = hi2(acc[r][1]);
        if (LAYER == 0) {
            const float* p0 = g_P0 + (size_t)s_cls[rl] * (4 * H_);
            gi += p0[0 * H_ + j]; gf += p0[1 * H_ + j];
            gg += p0[2 * H_ + j]; go += p0[3 * H_ + j];
        } else {
            gi += bias[0]; gf += bias[1]; gg += bias[2]; go += bias[3];
        }
        float cold = ccur[(size_t)s_src[rl] * H_ + j];
        float cn = f_sig(gf) * cold + f_sig(gi) * f_tanh(gg);
        float hn = f_sig(go) * f_tanh(cn);
        cnxt[(size_t)row_g * H_ + j] = cn;
        hnxt[(size_t)row_g * H_ + j] = hn;
        if (LAYER == 2)
            g_state[(size_t)row_g * H_ + j] = hn + x[(size_t)t_next * B_ * H_ + b * H_ + j];
    }
}

// ------------------------- output ------------------------------------------
__global__ void k_out(float* __restrict__ out, int n) {
    int i = blockIdx.x * 256 + threadIdx.x;
    if (i >= n) return;
    if (i < B_ * K_ * T_STEPS) out[i] = (float)g_choices[i];
    else if (i < B_ * K_ * T_STEPS + B_ * K_) out[i] = g_prefix[i - B_ * K_ * T_STEPS];
    else out[i] = 0.f;
}

// ------------------------- host --------------------------------------------
extern "C" void kernel_launch(void* const* d_in, const int* in_sizes, int n_in,
                              void* d_out, int out_size) {
    const float* x    = (const float*)d_in[0];
    const float* emb  = (const float*)d_in[1];
    const float* W_ih = (const float*)d_in[2];
    const float* W_hh = (const float*)d_in[3];
    const float* b_ih = (const float*)d_in[4];
    const float* b_hh = (const float*)d_in[5];
    const float* Wp   = (const float*)d_in[6];
    const float* bp   = (const float*)d_in[7];

    const int WSTRIDE = 4 * H_ * H_;
    const int BSTRIDE = 4 * H_;

    k_transpose<<<(H_ * C_) / 256, 256>>>(Wp);
    k_p0<<<C_, 256>>>(emb, W_ih, b_ih, b_hh);
    k_init_misc<<<(BK * H_) / 256, 256>>>(x);
    for (int l = 0; l < L_; l++)
        k_init_lstm<<<B_, 256>>>(x, W_ih + (size_t)l * WSTRIDE,
                                 b_ih + (size_t)l * BSTRIDE,
                                 b_hh + (size_t)l * BSTRIDE, l);

    dim3 g(8, 16);
    for (int t = 0; t < T_STEPS; t++) {
        int rb = t & 1;
        int t_next = (t + 1 < T_STEPS) ? (t + 1) : (T_STEPS - 1);
        k_proj<<<B_, 256>>>(bp, t);
        k_lstm<0><<<g, 256>>>(W_ih, W_hh, b_ih, b_hh, x, rb, t_next);
        k_lstm<1><<<g, 256>>>(W_ih + (size_t)1 * WSTRIDE, W_hh + (size_t)1 * WSTRIDE,
                              b_ih + (size_t)1 * BSTRIDE, b_hh + (size_t)1 * BSTRIDE,
                              x, rb, t_next);
        k_lstm<2><<<g, 256>>>(W_ih + (size_t)2 * WSTRIDE, W_hh + (size_t)2 * WSTRIDE,
                              b_ih + (size_t)2 * BSTRIDE, b_hh + (size_t)2 * BSTRIDE,
                              x, rb, t_next);
    }
    k_out<<<(out_size + 255) / 256, 256>>>((float*)d_out, out_size);
}